// round 11
// baseline (speedup 1.0000x reference)
#include <cuda_runtime.h>
#include <cstdint>

typedef unsigned long long u64;

// ---------- hardware tanh (1 MUFU op); sigmoid via tanh identity ----------
__device__ __forceinline__ float tanh_(float x) {
    float r;
    asm("tanh.approx.f32 %0, %1;" : "=f"(r) : "f"(x));
    return r;
}
__device__ __forceinline__ float sig_(float x) {
    return fmaf(0.5f, tanh_(0.5f * x), 0.5f);
}

// ---------- packed f32x2 primitives ----------
__device__ __forceinline__ u64 fma2(u64 a, u64 b, u64 c) {
    u64 d;
    asm("fma.rn.f32x2 %0, %1, %2, %3;" : "=l"(d) : "l"(a), "l"(b), "l"(c));
    return d;
}
__device__ __forceinline__ u64 mul2(u64 a, u64 b) {
    u64 d;
    asm("mul.rn.f32x2 %0, %1, %2;" : "=l"(d) : "l"(a), "l"(b));
    return d;
}
__device__ __forceinline__ u64 pk2(float lo, float hi) {
    u64 r;
    asm("mov.b64 %0, {%1, %2};" : "=l"(r) : "f"(lo), "f"(hi));
    return r;
}
__device__ __forceinline__ void upk2(u64 v, float& lo, float& hi) {
    asm("mov.b64 {%0, %1}, %2;" : "=f"(lo), "=f"(hi) : "l"(v));
}
__device__ __forceinline__ u64 tanh2p(u64 v) {
    float lo, hi; upk2(v, lo, hi);
    return pk2(tanh_(lo), tanh_(hi));
}
#define HALF2 0x3F0000003F000000ULL  // (0.5f, 0.5f)
__device__ __forceinline__ u64 sig2p(u64 v) {
    // sigmoid = 0.5*tanh(0.5x) + 0.5 (packed)
    return fma2(tanh2p(mul2(v, HALF2)), HALF2, HALF2);
}

// volatile shared loads: uncacheable, unhoistable -> kills weight caching
__device__ __forceinline__ void lds2u64(const float* p, u64& a, u64& b) {
    unsigned s = (unsigned)__cvta_generic_to_shared(p);
    asm volatile("ld.volatile.shared.v2.u64 {%0,%1}, [%2];"
                 : "=l"(a), "=l"(b) : "r"(s));
}
__device__ __forceinline__ u64 lds64v(const u64* p) {
    u64 v;
    unsigned s = (unsigned)__cvta_generic_to_shared(p);
    asm volatile("ld.volatile.shared.u64 %0, [%1];" : "=l"(v) : "r"(s));
    return v;
}
__device__ __forceinline__ float4 lds128v(const float* p) {
    float4 v;
    unsigned s = (unsigned)__cvta_generic_to_shared(p);
    asm volatile("ld.volatile.shared.v4.f32 {%0,%1,%2,%3}, [%4];"
                 : "=f"(v.x), "=f"(v.y), "=f"(v.z), "=f"(v.w)
                 : "r"(s));
    return v;
}

#define TT 14
#define HH 7
#define FF 12
#define NTHR 128

// ---------- shared phase-1 (coalesced linear1 + tanh) ----------
// Writes tanh(x.w1+b1) to caller-provided addressing via functor-free lambda:
// paired blocks write halves of u64 slots; scalar blocks write floats.

// ---------- packed full block: 256 elements, 2 per thread in f32x2 ----------
__device__ __forceinline__ void run_packed(
    const float* __restrict__ x, float* __restrict__ out, int B, int base,
    const float* s_l0p, const float* s_l1p, const float* s_w1,
    const float* s_w2p, float blin, float b2v, u64* s_up, int tid)
{
    const int nb = min(2 * NTHR, B - base);
    if (nb <= 0) return;
    const int cnt = nb * TT;

    // phase 1: write tanh(linear1) into (lo,hi) halves of u64 slots
    {
        float4 wA = *(const float4*)&s_w1[0];
        float4 wB = *(const float4*)&s_w1[4];
        float4 wC = *(const float4*)&s_w1[8];
        const float* xb = x + (long)base * TT * FF;
        float* uf = (float*)s_up;
        const int iters = (cnt + NTHR - 1) / NTHR;
#pragma unroll 1
        for (int it = 0; it < iters; it++) {
            int idx = it * NTHR + tid;
            if (idx < cnt) {
                int bl = idx / TT;
                int t  = idx - bl * TT;
                const float4* px = (const float4*)(xb + (long)idx * FF);
                float4 a0 = px[0], a1 = px[1], a2 = px[2];
                float s = blin;
                s = fmaf(a0.x, wA.x, s); s = fmaf(a0.y, wA.y, s);
                s = fmaf(a0.z, wA.z, s); s = fmaf(a0.w, wA.w, s);
                s = fmaf(a1.x, wB.x, s); s = fmaf(a1.y, wB.y, s);
                s = fmaf(a1.z, wB.z, s); s = fmaf(a1.w, wB.w, s);
                s = fmaf(a2.x, wC.x, s); s = fmaf(a2.y, wC.y, s);
                s = fmaf(a2.z, wC.z, s); s = fmaf(a2.w, wC.w, s);
                uf[(((bl & 127) * 15) + t) * 2 + (bl >> 7)] = tanh_(s);
            }
        }
    }
    __syncthreads();

    if (tid >= nb) return;
    const bool hasB = (NTHR + tid < nb);

    u64 h0[HH], c0[HH], h1[HH], c1[HH];
#pragma unroll
    for (int j = 0; j < HH; j++) { h0[j] = 0ull; c0[j] = 0ull; h1[j] = 0ull; c1[j] = 0ull; }

#pragma unroll 1
    for (int t = 0; t < TT; t++) {
        const u64 xin = lds64v(&s_up[tid * 15 + t]);

        // layer 0: per-j paired record [4 bias pairs | 4 x 8 weight pairs]
        u64 hn[HH];
#pragma unroll
        for (int j = 0; j < HH; j++) {
            const float* rec = &s_l0p[j * 72];
            u64 z[4];
            {
                u64 bi, bf, bg, bo;
                lds2u64(rec, bi, bf);
                lds2u64(rec + 4, bg, bo);
                z[0] = bi; z[1] = bf; z[2] = bg; z[3] = bo;
            }
#pragma unroll
            for (int g = 0; g < 4; g++) {
                const float* wp = rec + 8 + g * 16;
                u64 w0, w1, w2, w3, w4, w5, w6, w7;
                lds2u64(wp,      w0, w1);
                lds2u64(wp + 4,  w2, w3);
                lds2u64(wp + 8,  w4, w5);
                lds2u64(wp + 12, w6, w7);
                u64 zz = fma2(xin, w0, z[g]);
                zz = fma2(h0[0], w1, zz);
                zz = fma2(h0[1], w2, zz);
                zz = fma2(h0[2], w3, zz);
                zz = fma2(h0[3], w4, zz);
                zz = fma2(h0[4], w5, zz);
                zz = fma2(h0[5], w6, zz);
                zz = fma2(h0[6], w7, zz);
                z[g] = zz;
            }
            u64 cv = fma2(sig2p(z[1]), c0[j], mul2(sig2p(z[0]), tanh2p(z[2])));
            c0[j] = cv;
            hn[j] = mul2(sig2p(z[3]), tanh2p(cv));
        }

        // layer 1: row (g,j) = 16 u64 pairs [bias, wih0..6, whh0..6, pad]
        u64 hn1[HH];
#pragma unroll
        for (int j = 0; j < HH; j++) {
            u64 z[4];
#pragma unroll
            for (int g = 0; g < 4; g++) {
                const float* rp = &s_l1p[(g * HH + j) * 32];
                u64 p0, p1, p2, p3, p4, p5, p6, p7, p8, p9, p10, p11, p12, p13, p14, p15;
                lds2u64(rp,      p0, p1);
                lds2u64(rp + 4,  p2, p3);
                lds2u64(rp + 8,  p4, p5);
                lds2u64(rp + 12, p6, p7);
                lds2u64(rp + 16, p8, p9);
                lds2u64(rp + 20, p10, p11);
                lds2u64(rp + 24, p12, p13);
                lds2u64(rp + 28, p14, p15);
                (void)p15;
                u64 zz = p0;
                zz = fma2(hn[0], p1, zz);
                zz = fma2(hn[1], p2, zz);
                zz = fma2(hn[2], p3, zz);
                zz = fma2(hn[3], p4, zz);
                zz = fma2(hn[4], p5, zz);
                zz = fma2(hn[5], p6, zz);
                zz = fma2(hn[6], p7, zz);
                zz = fma2(h1[0], p8, zz);
                zz = fma2(h1[1], p9, zz);
                zz = fma2(h1[2], p10, zz);
                zz = fma2(h1[3], p11, zz);
                zz = fma2(h1[4], p12, zz);
                zz = fma2(h1[5], p13, zz);
                zz = fma2(h1[6], p14, zz);
                z[g] = zz;
            }
            u64 cv = fma2(sig2p(z[1]), c1[j], mul2(sig2p(z[0]), tanh2p(z[2])));
            c1[j] = cv;
            hn1[j] = mul2(sig2p(z[3]), tanh2p(cv));
        }

#pragma unroll
        for (int j = 0; j < HH; j++) { h0[j] = hn[j]; h1[j] = hn1[j]; }
    }

    // phase 3 (packed dot with duplicated w2 pairs)
    u64 acc = pk2(b2v, b2v);
#pragma unroll
    for (int j = 0; j < HH; j++) {
        u64 wa, wb;
        lds2u64(&s_w2p[j * 4], wa, wb);          // pairs 2j, 2j+1... layout below
        acc = fma2(h0[j], wa, acc);
        acc = fma2(h1[j], wb, acc);
    }
    float alo, ahi;
    upk2(acc, alo, ahi);
    out[base + tid] = alo;
    if (hasB) out[base + NTHR + tid] = ahi;
}

// ---------- scalar light block: 128 elements, 1 per thread ----------
__device__ __forceinline__ void run_light(
    const float* __restrict__ x, float* __restrict__ out, int B, int base,
    const float* s_l0s, const float* s_l1s, const float* s_w1,
    const float* s_w2, float blin, float b2v, float* s_u, int tid)
{
    const int nb = min(NTHR, B - base);
    if (nb <= 0) return;
    const int cnt = nb * TT;

    {
        float4 wA = *(const float4*)&s_w1[0];
        float4 wB = *(const float4*)&s_w1[4];
        float4 wC = *(const float4*)&s_w1[8];
        const float* xb = x + (long)base * TT * FF;
        const int iters = (cnt + NTHR - 1) / NTHR;
#pragma unroll 1
        for (int it = 0; it < iters; it++) {
            int idx = it * NTHR + tid;
            if (idx < cnt) {
                int bl = idx / TT;
                int t  = idx - bl * TT;
                const float4* px = (const float4*)(xb + (long)idx * FF);
                float4 a0 = px[0], a1 = px[1], a2 = px[2];
                float s = blin;
                s = fmaf(a0.x, wA.x, s); s = fmaf(a0.y, wA.y, s);
                s = fmaf(a0.z, wA.z, s); s = fmaf(a0.w, wA.w, s);
                s = fmaf(a1.x, wB.x, s); s = fmaf(a1.y, wB.y, s);
                s = fmaf(a1.z, wB.z, s); s = fmaf(a1.w, wB.w, s);
                s = fmaf(a2.x, wC.x, s); s = fmaf(a2.y, wC.y, s);
                s = fmaf(a2.z, wC.z, s); s = fmaf(a2.w, wC.w, s);
                s_u[bl * 15 + t] = tanh_(s);
            }
        }
    }
    __syncthreads();

    if (tid >= nb) return;

    float h0[HH], c0[HH], h1[HH], c1[HH];
#pragma unroll
    for (int j = 0; j < HH; j++) { h0[j] = 0.f; c0[j] = 0.f; h1[j] = 0.f; c1[j] = 0.f; }

#pragma unroll 1
    for (int t = 0; t < TT; t++) {
        const float xin = s_u[tid * 15 + t];

        float hn[HH];
#pragma unroll
        for (int j = 0; j < HH; j++) {
            const float* rec = &s_l0s[j * 36];
            float4 bz = lds128v(rec);
            const float bsel[4] = {bz.x, bz.y, bz.z, bz.w};
            float z[4];
#pragma unroll
            for (int g = 0; g < 4; g++) {
                float4 r0 = lds128v(rec + 4 + g * 8);
                float4 r1 = lds128v(rec + 8 + g * 8);
                float zz = fmaf(xin, r0.x, bsel[g]);
                zz = fmaf(h0[0], r0.y, zz);
                zz = fmaf(h0[1], r0.z, zz);
                zz = fmaf(h0[2], r0.w, zz);
                zz = fmaf(h0[3], r1.x, zz);
                zz = fmaf(h0[4], r1.y, zz);
                zz = fmaf(h0[5], r1.z, zz);
                zz = fmaf(h0[6], r1.w, zz);
                z[g] = zz;
            }
            float cv = fmaf(sig_(z[1]), c0[j], sig_(z[0]) * tanh_(z[2]));
            c0[j] = cv;
            hn[j] = sig_(z[3]) * tanh_(cv);
        }

        float hn1[HH];
#pragma unroll
        for (int j = 0; j < HH; j++) {
            float z[4];
#pragma unroll
            for (int g = 0; g < 4; g++) {
                const float* rp = &s_l1s[(g * HH + j) * 16];
                float4 r0 = lds128v(rp);
                float4 r1 = lds128v(rp + 4);
                float4 r2 = lds128v(rp + 8);
                float4 r3 = lds128v(rp + 12);
                float zz = r0.x;
                zz = fmaf(hn[0], r0.y, zz);
                zz = fmaf(hn[1], r0.z, zz);
                zz = fmaf(hn[2], r0.w, zz);
                zz = fmaf(hn[3], r1.x, zz);
                zz = fmaf(hn[4], r1.y, zz);
                zz = fmaf(hn[5], r1.z, zz);
                zz = fmaf(hn[6], r1.w, zz);
                zz = fmaf(h1[0], r2.x, zz);
                zz = fmaf(h1[1], r2.y, zz);
                zz = fmaf(h1[2], r2.z, zz);
                zz = fmaf(h1[3], r2.w, zz);
                zz = fmaf(h1[4], r3.x, zz);
                zz = fmaf(h1[5], r3.y, zz);
                zz = fmaf(h1[6], r3.z, zz);
                z[g] = zz;
            }
            float cv = fmaf(sig_(z[1]), c1[j], sig_(z[0]) * tanh_(z[2]));
            c1[j] = cv;
            hn1[j] = sig_(z[3]) * tanh_(cv);
        }

#pragma unroll
        for (int j = 0; j < HH; j++) { h0[j] = hn[j]; h1[j] = hn1[j]; }
    }

    float acc = b2v;
#pragma unroll
    for (int j = 0; j < HH; j++) {
        acc = fmaf(h0[j], s_w2[j], acc);
        acc = fmaf(h1[j], s_w2[HH + j], acc);
    }
    out[base + tid] = acc;
}

__global__ __launch_bounds__(NTHR, 4)
void lstm_fused_kernel(
    const float* __restrict__ x,
    const float* __restrict__ w1,  const float* __restrict__ b1,
    const float* __restrict__ wih0, const float* __restrict__ whh0,
    const float* __restrict__ bih0, const float* __restrict__ bhh0,
    const float* __restrict__ wih1, const float* __restrict__ whh1,
    const float* __restrict__ bih1, const float* __restrict__ bhh1,
    const float* __restrict__ w2,  const float* __restrict__ b2,
    float* __restrict__ out, int B, int nfull)
{
    // paired (duplicated) weights for packed blocks
    __shared__ __align__(16) float s_l0p[HH * 72];   // per j: 4 bias pairs + 4x8 weight pairs
    __shared__ __align__(16) float s_l1p[28 * 32];   // per row: bias,wih x7,whh x7 pairs + pad
    __shared__ __align__(16) float s_w2p[HH * 4];    // per j: (w2[j] dup, w2[7+j] dup)
    // scalar weights for light blocks
    __shared__ __align__(16) float s_l0s[HH * 36];
    __shared__ __align__(16) float s_l1s[28 * 16];
    __shared__ float s_w2[2 * HH];
    __shared__ __align__(16) float s_w1[12];
    __shared__ float s_b1lin, s_b2;
    __shared__ __align__(16) u64 s_up[NTHR * 15];    // packed u / scalar-aliased

    const int tid = threadIdx.x;

    for (int r = tid; r < 28; r += NTHR) {
        int g = r / 7, j = r % 7;
        float bsum0 = bih0[r] + bhh0[r];
        float bsum1 = bih1[r] + bhh1[r];

        // scalar layer0 record
        s_l0s[j * 36 + g] = bsum0;
        s_l0s[j * 36 + 4 + g * 8 + 0] = wih0[r];
#pragma unroll
        for (int k = 0; k < 7; k++) s_l0s[j * 36 + 4 + g * 8 + 1 + k] = whh0[r * 7 + k];

        // paired layer0 record
        s_l0p[j * 72 + g * 2 + 0] = bsum0;
        s_l0p[j * 72 + g * 2 + 1] = bsum0;
        {
            float* wp = &s_l0p[j * 72 + 8 + g * 16];
            wp[0] = wih0[r]; wp[1] = wih0[r];
#pragma unroll
            for (int k = 0; k < 7; k++) {
                float w = whh0[r * 7 + k];
                wp[2 + 2 * k] = w; wp[3 + 2 * k] = w;
            }
        }

        // scalar layer1 row
        s_l1s[r * 16 + 0] = bsum1;
#pragma unroll
        for (int k = 0; k < 7; k++) s_l1s[r * 16 + 1 + k] = wih1[r * 7 + k];
#pragma unroll
        for (int k = 0; k < 7; k++) s_l1s[r * 16 + 8 + k] = whh1[r * 7 + k];
        s_l1s[r * 16 + 15] = 0.f;

        // paired layer1 row
        {
            float* rp = &s_l1p[r * 32];
            rp[0] = bsum1; rp[1] = bsum1;
#pragma unroll
            for (int k = 0; k < 7; k++) {
                float w = wih1[r * 7 + k];
                rp[2 + 2 * k] = w; rp[3 + 2 * k] = w;
            }
#pragma unroll
            for (int k = 0; k < 7; k++) {
                float w = whh1[r * 7 + k];
                rp[16 + 2 * k] = w; rp[17 + 2 * k] = w;
            }
            rp[30] = 0.f; rp[31] = 0.f;
        }
    }
    if (tid < 2 * HH) s_w2[tid] = w2[tid];
    if (tid < HH) {
        s_w2p[tid * 4 + 0] = w2[tid];      s_w2p[tid * 4 + 1] = w2[tid];
        s_w2p[tid * 4 + 2] = w2[HH + tid]; s_w2p[tid * 4 + 3] = w2[HH + tid];
    }
    if (tid < FF)     s_w1[tid] = w1[tid];
    if (tid == 0) { s_b1lin = b1[0]; s_b2 = b2[0]; }
    __syncthreads();

    const int bid = blockIdx.x;
    if (bid < nfull) {
        run_packed(x, out, B, bid * (2 * NTHR),
                   s_l0p, s_l1p, s_w1, s_w2p, s_b1lin, s_b2, s_up, tid);
    } else {
        run_light(x, out, B, nfull * (2 * NTHR) + (bid - nfull) * NTHR,
                  s_l0s, s_l1s, s_w1, s_w2, s_b1lin, s_b2, (float*)s_up, tid);
    }
}

extern "C" void kernel_launch(void* const* d_in, const int* in_sizes, int n_in,
                              void* d_out, int out_size) {
    const float* x    = (const float*)d_in[0];
    const float* w1   = (const float*)d_in[1];
    const float* b1   = (const float*)d_in[2];
    const float* wih0 = (const float*)d_in[3];
    const float* whh0 = (const float*)d_in[4];
    const float* bih0 = (const float*)d_in[5];
    const float* bhh0 = (const float*)d_in[6];
    const float* wih1 = (const float*)d_in[7];
    const float* whh1 = (const float*)d_in[8];
    const float* bih1 = (const float*)d_in[9];
    const float* bhh1 = (const float*)d_in[10];
    const float* w2   = (const float*)d_in[11];
    const float* b2   = (const float*)d_in[12];
    float* out = (float*)d_out;

    const int B = out_size;                 // 262144

    int sms = 148;
    cudaDeviceGetAttribute(&sms, cudaDevAttrMultiProcessorCount, 0);

    int grid   = 2 * 4 * sms;                        // exact 2 waves @ 4/SM
    int chunks = (B + NTHR - 1) / NTHR;              // 2048 chunks of 128
    if (chunks > 2 * grid) grid = (chunks + 1) / 2;  // safety for huge B
    int nfull = chunks - grid;                       // packed (2-chunk) blocks
    if (nfull < 0) nfull = 0;
    if (nfull > grid) nfull = grid;

    lstm_fused_kernel<<<grid, NTHR>>>(x, w1, b1, wih0, whh0, bih0, bhh0,
                                      wih1, whh1, bih1, bhh1, w2, b2,
                                      out, B, nfull);
}

// round 12
// speedup vs baseline: 1.1737x; 1.1737x over previous
#include <cuda_runtime.h>
#include <cstdint>

// ---------- hardware tanh (1 MUFU op) ----------
__device__ __forceinline__ float tanh_(float x) {
    float r;
    asm("tanh.approx.f32 %0, %1;" : "=f"(r) : "f"(x));
    return r;
}

// volatile LDS.128: uncacheable, unhoistable -> kills ptxas weight-caching
__device__ __forceinline__ float4 lds128v(const float* p) {
    float4 v;
    unsigned saddr = (unsigned)__cvta_generic_to_shared(p);
    asm volatile("ld.volatile.shared.v4.f32 {%0,%1,%2,%3}, [%4];"
                 : "=f"(v.x), "=f"(v.y), "=f"(v.z), "=f"(v.w)
                 : "r"(saddr));
    return v;
}

#define TT 14
#define HH 7
#define FF 12
#define NTHR 128

// Gate-folded LSTM cell update. Weights pre-scaled so that:
//  - i,f,o rows produce z' = 0.5*z_true  (sigmoid = 0.5*tanh(z')+0.5)
//  - hidden state is carried as h' = 2*h_true (consumers pre-scaled by 0.5)
// 11 instructions per cell: 5 MUFU + 2 FFMA + FMUL + FFMA + FADD + FMUL.
__device__ __forceinline__ float cell_update(const float z[4], float& c) {
    float ti = tanh_(z[0]);
    float tf = tanh_(z[1]);
    float tg = tanh_(z[2]);
    float to = tanh_(z[3]);
    float iv = fmaf(0.5f, ti, 0.5f);
    float fv = fmaf(0.5f, tf, 0.5f);
    float cv = fmaf(fv, c, iv * tg);
    c = cv;
    return (to + 1.0f) * tanh_(cv);   // = 2*h_true
}

// EB-templated block body: EB=1 compiles with NO second chain.
template <int EB>
__device__ __forceinline__ void run_block(
    const float* __restrict__ x, float* __restrict__ out, int B, int base,
    const float* s_l0, const float* s_l1, const float* s_w1,
    const float* s_w2, float blin, float b2v, float* s_u, int tid)
{
    const int cap = EB * NTHR;
    const int nb = min(cap, B - base);   // block-uniform
    if (nb <= 0) return;
    const int cnt = nb * TT;

    // ---- phase 1: coalesced linear1 + tanh ----
    {
        float4 wA = *(const float4*)&s_w1[0];
        float4 wB = *(const float4*)&s_w1[4];
        float4 wC = *(const float4*)&s_w1[8];
        const float* xb = x + (long)base * TT * FF;
        const int iters = (cnt + NTHR - 1) / NTHR;
#pragma unroll 1
        for (int it = 0; it < iters; it++) {
            int idx = it * NTHR + tid;
            if (idx < cnt) {
                int bl = idx / TT;
                int t  = idx - bl * TT;
                const float4* px = (const float4*)(xb + (long)idx * FF);
                float4 a0 = px[0], a1 = px[1], a2 = px[2];
                float s = blin;
                s = fmaf(a0.x, wA.x, s); s = fmaf(a0.y, wA.y, s);
                s = fmaf(a0.z, wA.z, s); s = fmaf(a0.w, wA.w, s);
                s = fmaf(a1.x, wB.x, s); s = fmaf(a1.y, wB.y, s);
                s = fmaf(a1.z, wB.z, s); s = fmaf(a1.w, wB.w, s);
                s = fmaf(a2.x, wC.x, s); s = fmaf(a2.y, wC.y, s);
                s = fmaf(a2.z, wC.z, s); s = fmaf(a2.w, wC.w, s);
                s_u[bl * 15 + t] = tanh_(s);
            }
        }
    }
    __syncthreads();

    if (tid >= nb) return;

    int ur[EB];
#pragma unroll
    for (int e = 0; e < EB; e++) ur[e] = min(e * NTHR + tid, nb - 1);

    float h0[EB][HH], c0[EB][HH], h1[EB][HH], c1[EB][HH];
#pragma unroll
    for (int e = 0; e < EB; e++)
#pragma unroll
        for (int j = 0; j < HH; j++) {
            h0[e][j] = 0.f; c0[e][j] = 0.f; h1[e][j] = 0.f; c1[e][j] = 0.f;
        }

#pragma unroll 1
    for (int t = 0; t < TT; t++) {
        float xin[EB];
#pragma unroll
        for (int e = 0; e < EB; e++) xin[e] = s_u[ur[e] * 15 + t];

        // ---- layer 0: per j, merged record [b_i,b_f,b_g,b_o | 4 x (wih, whh0..6)]
        float hn[EB][HH];
#pragma unroll
        for (int j = 0; j < HH; j++) {
            const float* rec = &s_l0[j * 36];
            float4 bz = lds128v(rec);
            const float bsel[4] = {bz.x, bz.y, bz.z, bz.w};
            float z[EB][4];
#pragma unroll
            for (int g = 0; g < 4; g++) {
                float4 r0 = lds128v(rec + 4 + g * 8);
                float4 r1 = lds128v(rec + 8 + g * 8);
#pragma unroll
                for (int e = 0; e < EB; e++) {
                    float zz = fmaf(xin[e], r0.x, bsel[g]);
                    zz = fmaf(h0[e][0], r0.y, zz);
                    zz = fmaf(h0[e][1], r0.z, zz);
                    zz = fmaf(h0[e][2], r0.w, zz);
                    zz = fmaf(h0[e][3], r1.x, zz);
                    zz = fmaf(h0[e][4], r1.y, zz);
                    zz = fmaf(h0[e][5], r1.z, zz);
                    zz = fmaf(h0[e][6], r1.w, zz);
                    z[e][g] = zz;
                }
            }
#pragma unroll
            for (int e = 0; e < EB; e++)
                hn[e][j] = cell_update(z[e], c0[e][j]);
        }

        // ---- layer 1: row r = g*7+j, 16 floats [b, wih0..6, whh0..6, pad]
        float hn1[EB][HH];
#pragma unroll
        for (int j = 0; j < HH; j++) {
            float z[EB][4];
#pragma unroll
            for (int g = 0; g < 4; g++) {
                const float* rp = &s_l1[(g * HH + j) * 16];
                float4 r0 = lds128v(rp);
                float4 r1 = lds128v(rp + 4);
                float4 r2 = lds128v(rp + 8);
                float4 r3 = lds128v(rp + 12);
#pragma unroll
                for (int e = 0; e < EB; e++) {
                    float zz = r0.x;
                    zz = fmaf(hn[e][0], r0.y, zz);
                    zz = fmaf(hn[e][1], r0.z, zz);
                    zz = fmaf(hn[e][2], r0.w, zz);
                    zz = fmaf(hn[e][3], r1.x, zz);
                    zz = fmaf(hn[e][4], r1.y, zz);
                    zz = fmaf(hn[e][5], r1.z, zz);
                    zz = fmaf(hn[e][6], r1.w, zz);
                    zz = fmaf(h1[e][0], r2.x, zz);
                    zz = fmaf(h1[e][1], r2.y, zz);
                    zz = fmaf(h1[e][2], r2.z, zz);
                    zz = fmaf(h1[e][3], r2.w, zz);
                    zz = fmaf(h1[e][4], r3.x, zz);
                    zz = fmaf(h1[e][5], r3.y, zz);
                    zz = fmaf(h1[e][6], r3.z, zz);
                    z[e][g] = zz;
                }
            }
#pragma unroll
            for (int e = 0; e < EB; e++)
                hn1[e][j] = cell_update(z[e], c1[e][j]);
        }

#pragma unroll
        for (int e = 0; e < EB; e++)
#pragma unroll
            for (int j = 0; j < HH; j++) {
                h0[e][j] = hn[e][j]; h1[e][j] = hn1[e][j];
            }
    }

    // ---- phase 3 (s_w2 pre-scaled by 0.5 to undo h' = 2h) ----
#pragma unroll
    for (int e = 0; e < EB; e++) {
        float acc = b2v;
#pragma unroll
        for (int j = 0; j < HH; j++) {
            acc = fmaf(h0[e][j], s_w2[j], acc);
            acc = fmaf(h1[e][j], s_w2[HH + j], acc);
        }
        int gb = base + e * NTHR + tid;
        if (gb < B) out[gb] = acc;
    }
}

__global__ __launch_bounds__(NTHR, 4)
void lstm_fused_kernel(
    const float* __restrict__ x,
    const float* __restrict__ w1,  const float* __restrict__ b1,
    const float* __restrict__ wih0, const float* __restrict__ whh0,
    const float* __restrict__ bih0, const float* __restrict__ bhh0,
    const float* __restrict__ wih1, const float* __restrict__ whh1,
    const float* __restrict__ bih1, const float* __restrict__ bhh1,
    const float* __restrict__ w2,  const float* __restrict__ b2,
    float* __restrict__ out, int B, int nfull)
{
    // layer0 per-j record: 36 floats [4 biases][4 x (wih, whh0..6)], pre-scaled
    __shared__ __align__(16) float s_l0[HH * 36];
    // layer1 row r, 16 floats: [b1[r], wih1[r][0..6], whh1[r][0..6], pad], pre-scaled
    __shared__ __align__(16) float s_l1[28 * 16];
    __shared__ __align__(16) float s_w1[12];
    __shared__ float s_w2[2 * HH];
    __shared__ float s_b1lin, s_b2;
    __shared__ float s_u[2 * NTHR * 15];

    const int tid = threadIdx.x;

    for (int r = tid; r < 28; r += NTHR) {
        int g = r / 7, j = r % 7;
        // gate g: 0=i, 1=f, 2=g(cell), 3=o
        const bool ifo = (g != 2);
        // sigmoid fold: i,f,o rows scaled 0.5. hidden rescale h'=2h: any weight
        // multiplying a hidden value gets x0.5 more.
        const float sb = ifo ? 0.5f : 1.0f;     // bias scale
        const float sx = ifo ? 0.5f : 1.0f;     // non-hidden-input weight scale
        const float sh = ifo ? 0.25f : 0.5f;    // hidden-input weight scale

        // layer0: input is u (true tanh, unscaled) -> sx; hidden h0' -> sh
        s_l0[j * 36 + g] = (bih0[r] + bhh0[r]) * sb;
        s_l0[j * 36 + 4 + g * 8 + 0] = wih0[r] * sx;
#pragma unroll
        for (int k = 0; k < 7; k++)
            s_l0[j * 36 + 4 + g * 8 + 1 + k] = whh0[r * 7 + k] * sh;

        // layer1: input is hn' (=2h) -> sh; hidden h1' -> sh
        s_l1[r * 16 + 0] = (bih1[r] + bhh1[r]) * sb;
#pragma unroll
        for (int k = 0; k < 7; k++) s_l1[r * 16 + 1 + k] = wih1[r * 7 + k] * sh;
#pragma unroll
        for (int k = 0; k < 7; k++) s_l1[r * 16 + 8 + k] = whh1[r * 7 + k] * sh;
        s_l1[r * 16 + 15] = 0.f;
    }
    if (tid < 2 * HH) s_w2[tid] = w2[tid] * 0.5f;   // undo h' = 2h
    if (tid < FF)     s_w1[tid] = w1[tid];
    if (tid == 0) { s_b1lin = b1[0]; s_b2 = b2[0]; }
    __syncthreads();

    const int bid = blockIdx.x;
    if (bid < nfull) {
        run_block<2>(x, out, B, bid * (2 * NTHR),
                     s_l0, s_l1, s_w1, s_w2, s_b1lin, s_b2, s_u, tid);
    } else {
        run_block<1>(x, out, B, nfull * (2 * NTHR) + (bid - nfull) * NTHR,
                     s_l0, s_l1, s_w1, s_w2, s_b1lin, s_b2, s_u, tid);
    }
}

extern "C" void kernel_launch(void* const* d_in, const int* in_sizes, int n_in,
                              void* d_out, int out_size) {
    const float* x    = (const float*)d_in[0];
    const float* w1   = (const float*)d_in[1];
    const float* b1   = (const float*)d_in[2];
    const float* wih0 = (const float*)d_in[3];
    const float* whh0 = (const float*)d_in[4];
    const float* bih0 = (const float*)d_in[5];
    const float* bhh0 = (const float*)d_in[6];
    const float* wih1 = (const float*)d_in[7];
    const float* whh1 = (const float*)d_in[8];
    const float* bih1 = (const float*)d_in[9];
    const float* bhh1 = (const float*)d_in[10];
    const float* w2   = (const float*)d_in[11];
    const float* b2   = (const float*)d_in[12];
    float* out = (float*)d_out;

    const int B = out_size;                 // 262144

    int sms = 148;
    cudaDeviceGetAttribute(&sms, cudaDevAttrMultiProcessorCount, 0);

    int grid   = 2 * 4 * sms;                        // exact 2 waves @ 4/SM
    int chunks = (B + NTHR - 1) / NTHR;              // 2048 chunks of 128
    if (chunks > 2 * grid) grid = (chunks + 1) / 2;  // safety for huge B
    int nfull = chunks - grid;                       // EB=2 blocks
    if (nfull < 0) nfull = 0;
    if (nfull > grid) nfull = grid;

    lstm_fused_kernel<<<grid, NTHR>>>(x, w1, b1, wih0, whh0, bih0, bhh0,
                                      wih1, whh1, bih1, bhh1, w2, b2,
                                      out, B, nfull);
}